// round 5
// baseline (speedup 1.0000x reference)
#include <cuda_runtime.h>
#include <cuda_bf16.h>
#include <math.h>

// Problem constants
constexpr int BATCH = 4;
constexpr int CIN   = 128;
constexpr int COUT  = 64;
constexpr int HH    = 128;
constexpr int WW    = 128;
constexpr int HWSZ  = HH * WW;
constexpr int DG    = 16;
constexpr int KK    = 9;

// Scratch (static device buffers; allocation APIs are forbidden)
__device__ float g_t1[(size_t)BATCH * COUT * HWSZ];
__device__ float g_t2[(size_t)BATCH * COUT * HWSZ];
__device__ float g_o4[(size_t)BATCH * (27 * DG) * HWSZ];      // 432 channels
__device__ __align__(16) float g_wt[(size_t)CIN * KK * COUT]; // transposed deform weight [cin][k][o]

// ---------------------------------------------------------------------------
// Packed f32x2 helpers (sm_103a FFMA2 path)
// ---------------------------------------------------------------------------
typedef unsigned long long u64;

__device__ __forceinline__ u64 ffma2(u64 a, u64 b, u64 c) {
    u64 d;
    asm("fma.rn.f32x2 %0, %1, %2, %3;" : "=l"(d) : "l"(a), "l"(b), "l"(c));
    return d;
}
__device__ __forceinline__ u64 pk2(float lo, float hi) {
    u64 r;
    asm("mov.b64 %0, {%1, %2};" : "=l"(r) : "f"(lo), "f"(hi));
    return r;
}
__device__ __forceinline__ float2 upk(u64 v) {
    float2 r;
    asm("mov.b64 {%0, %1}, %2;" : "=f"(r.x), "=f"(r.y) : "l"(v));
    return r;
}
__device__ __forceinline__ float fast_tanh(float x) {
    // tanh(x) = 1 - 2/(exp(2x)+1)
    return 1.f - 2.f / (__expf(2.f * x) + 1.f);
}
__device__ __forceinline__ float fast_sigmoid(float x) {
    return 1.f / (1.f + __expf(-x));
}

// ---------------------------------------------------------------------------
// Transpose deform weight (COUT, CIN, 3, 3) -> [cin][k][o]
// ---------------------------------------------------------------------------
__global__ void transpose_weight_k(const float* __restrict__ w, float* __restrict__ wt) {
    int idx = blockIdx.x * blockDim.x + threadIdx.x;
    int n = CIN * KK * COUT;
    if (idx >= n) return;
    int o   = idx % COUT;
    int k   = (idx / COUT) % KK;
    int cin = idx / (COUT * KK);
    wt[idx] = w[((size_t)o * CIN + cin) * KK + k];
}

// ---------------------------------------------------------------------------
// Direct 3x3 conv, pad=1, stride=1, optional leaky-relu(0.1). (unchanged R4)
// ---------------------------------------------------------------------------
__global__ void __launch_bounds__(128, 4)
conv3x3_k(const float* __restrict__ in, const float* __restrict__ wgt,
          const float* __restrict__ bias, float* __restrict__ out,
          int Cin, int Cout_, int lrelu) {
    const int tx   = threadIdx.x;        // 0..31
    const int ty   = threadIdx.y;        // 0..3
    const int tid  = ty * 32 + tx;
    const int lane = tid & 31;
    const int warp = tid >> 5;
    const int y0   = blockIdx.x * 8;
    const int oc0  = blockIdx.y * 8;
    const int b    = blockIdx.z;
    const int px0  = tx * 4;

    __shared__ __align__(16) float s_E[2][2][10][132];  // [buf][ch][row][pos]
    __shared__ __align__(16) float s_O[2][2][10][132];
    __shared__ __align__(16) u64   s_w[2][2][9][8];     // [buf][ch][k][o] dup-packed

    for (int i = tid; i < 40; i += 128) {
        int bu = i / 20, ch = (i / 10) % 2, t = i % 10;
        s_O[bu][ch][t][0]   = 0.f;
        s_O[bu][ch][t][129] = 0.f;
    }

    u64 acc[8][2][2];
#pragma unroll
    for (int o = 0; o < 8; o++)
#pragma unroll
        for (int i = 0; i < 2; i++) { acc[o][i][0] = 0ull; acc[o][i][1] = 0ull; }

    const float* inb = in + (size_t)b * Cin * HWSZ;

    auto load_stage = [&](int buf, int ci) {
#pragma unroll
        for (int rr = warp; rr < 20; rr += 4) {
            int ch = rr / 10, t = rr % 10;
            int gy = y0 - 1 + t;
            float4 v = make_float4(0.f, 0.f, 0.f, 0.f);
            if (gy >= 0 && gy < HH) {
                const float* src = inb + (size_t)(ci + ch) * HWSZ + gy * WW;
                v = ((const float4*)src)[lane];
            }
            *((float4*)&s_E[buf][ch][t][lane * 4]) = v;
            float* dO = &s_O[buf][ch][t][lane * 4 + 1];
            dO[0] = v.x; dO[1] = v.y; dO[2] = v.z; dO[3] = v.w;
        }
        for (int i = tid; i < 144; i += 128) {
            int ch = i / 72, r = i % 72;
            int k = r / 8, o = r % 8;
            float w = wgt[((size_t)(oc0 + o) * Cin + ci + ch) * 9 + k];
            s_w[buf][ch][k][o] = pk2(w, w);
        }
    };

    load_stage(0, 0);
    __syncthreads();

    for (int ci = 0; ci < Cin; ci += 2) {
        const int buf = (ci >> 1) & 1;
        if (ci + 2 < Cin) load_stage(buf ^ 1, ci + 2);

#pragma unroll
        for (int ch = 0; ch < 2; ch++) {
            u64 p[4][5];
#pragma unroll
            for (int r = 0; r < 4; r++) {
                const u64* rowE = (const u64*)&s_E[buf][ch][ty * 2 + r][px0];
                const u64* rowO = (const u64*)&s_O[buf][ch][ty * 2 + r][px0];
                p[r][1] = rowE[0];
                p[r][3] = rowE[1];
                p[r][0] = rowO[0];
                p[r][2] = rowO[1];
                p[r][4] = rowO[2];
            }
#pragma unroll
            for (int k = 0; k < 9; k++) {
                const int r = k / 3, s = k % 3;
                const ulonglong2* wk = (const ulonglong2*)&s_w[buf][ch][k][0];
#pragma unroll
                for (int op = 0; op < 4; op++) {
                    ulonglong2 wq = wk[op];
                    const int o0 = 2 * op, o1 = 2 * op + 1;
                    acc[o0][0][0] = ffma2(p[r + 0][s],     wq.x, acc[o0][0][0]);
                    acc[o0][0][1] = ffma2(p[r + 0][s + 2], wq.x, acc[o0][0][1]);
                    acc[o0][1][0] = ffma2(p[r + 1][s],     wq.x, acc[o0][1][0]);
                    acc[o0][1][1] = ffma2(p[r + 1][s + 2], wq.x, acc[o0][1][1]);
                    acc[o1][0][0] = ffma2(p[r + 0][s],     wq.y, acc[o1][0][0]);
                    acc[o1][0][1] = ffma2(p[r + 0][s + 2], wq.y, acc[o1][0][1]);
                    acc[o1][1][0] = ffma2(p[r + 1][s],     wq.y, acc[o1][1][0]);
                    acc[o1][1][1] = ffma2(p[r + 1][s + 2], wq.y, acc[o1][1][1]);
                }
            }
        }
        __syncthreads();
    }

#pragma unroll
    for (int o = 0; o < 8; o++) {
        float bv = bias[oc0 + o];
#pragma unroll
        for (int i = 0; i < 2; i++) {
            int yy = y0 + ty * 2 + i;
            float* op = out + ((size_t)b * Cout_ + oc0 + o) * HWSZ + yy * WW + px0;
#pragma unroll
            for (int jp = 0; jp < 2; jp++) {
                float2 v = upk(acc[o][i][jp]);
                v.x += bv; v.y += bv;
                if (lrelu) {
                    v.x = (v.x >= 0.f) ? v.x : 0.1f * v.x;
                    v.y = (v.y >= 0.f) ? v.y : 0.1f * v.y;
                }
                ((float2*)op)[jp] = v;
            }
        }
    }
}

// ---------------------------------------------------------------------------
// Deformable conv v2 (fused tanh/sigmoid), 2 pixels per thread.
// Thread = pixels (py, px) and (py+4, px); 2 x 64 oc accumulators as 64 f32x2.
// Per (c,k): 16 broadcast LDS.128 feed 8 FFMA2 each (2px x 2oc x 2lanes).
// Gather values for all 8 channels batched before the weight loop (MLP).
// blockDim = (32,4); grid = (W/32, H/8, B) = 256 CTAs.
// ---------------------------------------------------------------------------
__global__ void __launch_bounds__(128, 2)
deform_k(const float* __restrict__ x, const float* __restrict__ o4,
         const float* __restrict__ wt, const float* __restrict__ bias,
         float* __restrict__ out) {
    const int tx = threadIdx.x, ty = threadIdx.y;
    const int tid = ty * 32 + tx;
    const int b   = blockIdx.z;
    const int px  = blockIdx.x * 32 + tx;
    const int py0 = blockIdx.y * 8 + ty;   // pixel 0 row
    const int py1 = py0 + 4;               // pixel 1 row
    const int p0  = py0 * WW + px;
    const int p1  = py1 * WW + px;

    __shared__ __align__(16) u64 s_w[8 * 9 * 32];  // [c][k][oc-pair]

    u64 acc0[32], acc1[32];
#pragma unroll
    for (int q = 0; q < 32; q++) { acc0[q] = 0ull; acc1[q] = 0ull; }

    const float* xb = x + (size_t)b * CIN * HWSZ;
    const float* ob = o4 + (size_t)b * (27 * DG) * HWSZ;

    for (int g = 0; g < DG; g++) {
        __syncthreads();
        const u64* wg = (const u64*)(wt + (size_t)g * 8 * 9 * 64);
        for (int i = tid; i < 8 * 9 * 32; i += 128) s_w[i] = wg[i];
        __syncthreads();

        const float* xg = xb + (size_t)g * 8 * HWSZ;

        for (int k = 0; k < KK; k++) {
            const float kio = (float)(k / 3) - 1.f;
            const float kjo = (float)(k % 3) - 1.f;
            const float* po_y = ob + (size_t)(g * 18 + 2 * k) * HWSZ;
            const float* po_x = ob + (size_t)(g * 18 + 2 * k + 1) * HWSZ;
            const float* po_m = ob + (size_t)(288 + g * 9 + k) * HWSZ;

            // --- per-pixel tap geometry ---
            float w00[2], w01[2], w10[2], w11[2];
            int   i00[2], i01[2], i10[2], i11[2];
#pragma unroll
            for (int j = 0; j < 2; j++) {
                const int p  = j ? p1 : p0;
                const int py = j ? py1 : py0;
                float dy = 10.f * fast_tanh(po_y[p]);
                float dx = 10.f * fast_tanh(po_x[p]);
                float m  = fast_sigmoid(po_m[p]);

                float fy = (float)py + kio + dy;
                float fx = (float)px + kjo + dx;
                float y0f = floorf(fy), x0f = floorf(fx);
                float ly = fy - y0f, lx = fx - x0f;
                int y0 = (int)y0f, x0 = (int)x0f;
                int y1 = y0 + 1, x1 = x0 + 1;

                bool vy0 = (y0 >= 0) && (y0 < HH);
                bool vy1 = (y1 >= 0) && (y1 < HH);
                bool vx0 = (x0 >= 0) && (x0 < WW);
                bool vx1 = (x1 >= 0) && (x1 < WW);

                w00[j] = (1.f - ly) * (1.f - lx) * ((vy0 && vx0) ? m : 0.f);
                w01[j] = (1.f - ly) * lx         * ((vy0 && vx1) ? m : 0.f);
                w10[j] = ly * (1.f - lx)         * ((vy1 && vx0) ? m : 0.f);
                w11[j] = ly * lx                 * ((vy1 && vx1) ? m : 0.f);

                int yc0 = min(max(y0, 0), HH - 1);
                int yc1 = min(max(y1, 0), HH - 1);
                int xc0 = min(max(x0, 0), WW - 1);
                int xc1 = min(max(x1, 0), WW - 1);
                i00[j] = yc0 * WW + xc0; i01[j] = yc0 * WW + xc1;
                i10[j] = yc1 * WW + xc0; i11[j] = yc1 * WW + xc1;
            }

            // --- batched gathers: all 8 channels, both pixels ---
            float v0[8], v1[8];
#pragma unroll
            for (int c = 0; c < 8; c++) {
                const float* xc = xg + (size_t)c * HWSZ;
                v0[c] = w00[0] * __ldg(&xc[i00[0]]) + w01[0] * __ldg(&xc[i01[0]])
                      + w10[0] * __ldg(&xc[i10[0]]) + w11[0] * __ldg(&xc[i11[0]]);
                v1[c] = w00[1] * __ldg(&xc[i00[1]]) + w01[1] * __ldg(&xc[i01[1]])
                      + w10[1] * __ldg(&xc[i10[1]]) + w11[1] * __ldg(&xc[i11[1]]);
            }

            // --- weight loop: 1 LDS.128 -> 8 FFMA2 ---
#pragma unroll
            for (int c = 0; c < 8; c++) {
                u64 v20 = pk2(v0[c], v0[c]);
                u64 v21 = pk2(v1[c], v1[c]);
                const ulonglong2* wp = (const ulonglong2*)&s_w[(c * 9 + k) * 32];
#pragma unroll
                for (int q = 0; q < 16; q++) {
                    ulonglong2 wq = wp[q];
                    acc0[q * 2 + 0] = ffma2(v20, wq.x, acc0[q * 2 + 0]);
                    acc0[q * 2 + 1] = ffma2(v20, wq.y, acc0[q * 2 + 1]);
                    acc1[q * 2 + 0] = ffma2(v21, wq.x, acc1[q * 2 + 0]);
                    acc1[q * 2 + 1] = ffma2(v21, wq.y, acc1[q * 2 + 1]);
                }
            }
        }
    }

    float* outb0 = out + (size_t)b * COUT * HWSZ + p0;
    float* outb1 = out + (size_t)b * COUT * HWSZ + p1;
#pragma unroll
    for (int q = 0; q < 32; q++) {
        float2 bv = ((const float2*)bias)[q];
        float2 a = upk(acc0[q]);
        float2 c = upk(acc1[q]);
        outb0[(size_t)(2 * q + 0) * HWSZ] = a.x + bv.x;
        outb0[(size_t)(2 * q + 1) * HWSZ] = a.y + bv.y;
        outb1[(size_t)(2 * q + 0) * HWSZ] = c.x + bv.x;
        outb1[(size_t)(2 * q + 1) * HWSZ] = c.y + bv.y;
    }
}

// ---------------------------------------------------------------------------
// Launcher
// ---------------------------------------------------------------------------
extern "C" void kernel_launch(void* const* d_in, const int* in_sizes, int n_in,
                              void* d_out, int out_size) {
    const float* x          = (const float*)d_in[0];
    const float* extra_feat = (const float*)d_in[1];
    const float* w1 = (const float*)d_in[2];
    const float* b1 = (const float*)d_in[3];
    const float* w2 = (const float*)d_in[4];
    const float* b2 = (const float*)d_in[5];
    const float* w3 = (const float*)d_in[6];
    const float* b3 = (const float*)d_in[7];
    const float* w4 = (const float*)d_in[8];
    const float* b4 = (const float*)d_in[9];
    const float* weight = (const float*)d_in[10];
    const float* bias   = (const float*)d_in[11];
    float* out = (float*)d_out;

    float *t1, *t2, *o4, *wt;
    cudaGetSymbolAddress((void**)&t1, g_t1);
    cudaGetSymbolAddress((void**)&t2, g_t2);
    cudaGetSymbolAddress((void**)&o4, g_o4);
    cudaGetSymbolAddress((void**)&wt, g_wt);

    dim3 blk(32, 4);

    // Transpose deform weight (only consumer is deform_k, last kernel)
    {
        int n = CIN * KK * COUT;
        transpose_weight_k<<<(n + 255) / 256, 256>>>(weight, wt);
    }

    // conv1: extra_feat (192ch) -> t1 (64ch), lrelu
    conv3x3_k<<<dim3(HH / 8, COUT / 8, BATCH), blk>>>(extra_feat, w1, b1, t1, 3 * COUT, COUT, 1);
    // conv2: t1 -> t2, lrelu
    conv3x3_k<<<dim3(HH / 8, COUT / 8, BATCH), blk>>>(t1, w2, b2, t2, COUT, COUT, 1);
    // conv3: t2 -> t1, lrelu
    conv3x3_k<<<dim3(HH / 8, COUT / 8, BATCH), blk>>>(t2, w3, b3, t1, COUT, COUT, 1);
    // conv4: t1 -> o4 (432ch), no activation (fused into deform)
    conv3x3_k<<<dim3(HH / 8, (27 * DG) / 8, BATCH), blk>>>(t1, w4, b4, o4, COUT, 27 * DG, 0);
    // deformable conv: x + o4 -> out (2 px/thread)
    deform_k<<<dim3(WW / 32, HH / 8, BATCH), blk>>>(x, o4, wt, bias, out);
}

// round 6
// speedup vs baseline: 1.0565x; 1.0565x over previous
#include <cuda_runtime.h>
#include <cuda_bf16.h>
#include <math.h>

// Problem constants
constexpr int BATCH = 4;
constexpr int CIN   = 128;
constexpr int COUT  = 64;
constexpr int HH    = 128;
constexpr int WW    = 128;
constexpr int HWSZ  = HH * WW;
constexpr int DG    = 16;
constexpr int KK    = 9;

// Scratch (static device buffers; allocation APIs are forbidden)
__device__ float g_t1[(size_t)BATCH * COUT * HWSZ];
__device__ float g_t2[(size_t)BATCH * COUT * HWSZ];
__device__ float g_o4[(size_t)BATCH * (27 * DG) * HWSZ];      // 432 channels
__device__ __align__(16) float g_wt[(size_t)CIN * KK * COUT]; // transposed deform weight [cin][k][o]

// ---------------------------------------------------------------------------
// Packed f32x2 helpers (sm_103a FFMA2 path)
// ---------------------------------------------------------------------------
typedef unsigned long long u64;

__device__ __forceinline__ u64 ffma2(u64 a, u64 b, u64 c) {
    u64 d;
    asm("fma.rn.f32x2 %0, %1, %2, %3;" : "=l"(d) : "l"(a), "l"(b), "l"(c));
    return d;
}
__device__ __forceinline__ u64 pk2(float lo, float hi) {
    u64 r;
    asm("mov.b64 %0, {%1, %2};" : "=l"(r) : "f"(lo), "f"(hi));
    return r;
}
__device__ __forceinline__ float2 upk(u64 v) {
    float2 r;
    asm("mov.b64 {%0, %1}, %2;" : "=f"(r.x), "=f"(r.y) : "l"(v));
    return r;
}
__device__ __forceinline__ float fast_tanh(float x) {
    // tanh(x) = 1 - 2/(exp(2x)+1)
    return 1.f - 2.f / (__expf(2.f * x) + 1.f);
}
__device__ __forceinline__ float fast_sigmoid(float x) {
    return 1.f / (1.f + __expf(-x));
}

// ---------------------------------------------------------------------------
// Transpose deform weight (COUT, CIN, 3, 3) -> [cin][k][o]
// ---------------------------------------------------------------------------
__global__ void transpose_weight_k(const float* __restrict__ w, float* __restrict__ wt) {
    int idx = blockIdx.x * blockDim.x + threadIdx.x;
    int n = CIN * KK * COUT;
    if (idx >= n) return;
    int o   = idx % COUT;
    int k   = (idx / COUT) % KK;
    int cin = idx / (COUT * KK);
    wt[idx] = w[((size_t)o * CIN + cin) * KK + k];
}

// ---------------------------------------------------------------------------
// Direct 3x3 conv, pad=1, stride=1, optional leaky-relu(0.1). (unchanged R4)
// ---------------------------------------------------------------------------
__global__ void __launch_bounds__(128, 4)
conv3x3_k(const float* __restrict__ in, const float* __restrict__ wgt,
          const float* __restrict__ bias, float* __restrict__ out,
          int Cin, int Cout_, int lrelu) {
    const int tx   = threadIdx.x;        // 0..31
    const int ty   = threadIdx.y;        // 0..3
    const int tid  = ty * 32 + tx;
    const int lane = tid & 31;
    const int warp = tid >> 5;
    const int y0   = blockIdx.x * 8;
    const int oc0  = blockIdx.y * 8;
    const int b    = blockIdx.z;
    const int px0  = tx * 4;

    __shared__ __align__(16) float s_E[2][2][10][132];  // [buf][ch][row][pos]
    __shared__ __align__(16) float s_O[2][2][10][132];
    __shared__ __align__(16) u64   s_w[2][2][9][8];     // [buf][ch][k][o] dup-packed

    for (int i = tid; i < 40; i += 128) {
        int bu = i / 20, ch = (i / 10) % 2, t = i % 10;
        s_O[bu][ch][t][0]   = 0.f;
        s_O[bu][ch][t][129] = 0.f;
    }

    u64 acc[8][2][2];
#pragma unroll
    for (int o = 0; o < 8; o++)
#pragma unroll
        for (int i = 0; i < 2; i++) { acc[o][i][0] = 0ull; acc[o][i][1] = 0ull; }

    const float* inb = in + (size_t)b * Cin * HWSZ;

    auto load_stage = [&](int buf, int ci) {
#pragma unroll
        for (int rr = warp; rr < 20; rr += 4) {
            int ch = rr / 10, t = rr % 10;
            int gy = y0 - 1 + t;
            float4 v = make_float4(0.f, 0.f, 0.f, 0.f);
            if (gy >= 0 && gy < HH) {
                const float* src = inb + (size_t)(ci + ch) * HWSZ + gy * WW;
                v = ((const float4*)src)[lane];
            }
            *((float4*)&s_E[buf][ch][t][lane * 4]) = v;
            float* dO = &s_O[buf][ch][t][lane * 4 + 1];
            dO[0] = v.x; dO[1] = v.y; dO[2] = v.z; dO[3] = v.w;
        }
        for (int i = tid; i < 144; i += 128) {
            int ch = i / 72, r = i % 72;
            int k = r / 8, o = r % 8;
            float w = wgt[((size_t)(oc0 + o) * Cin + ci + ch) * 9 + k];
            s_w[buf][ch][k][o] = pk2(w, w);
        }
    };

    load_stage(0, 0);
    __syncthreads();

    for (int ci = 0; ci < Cin; ci += 2) {
        const int buf = (ci >> 1) & 1;
        if (ci + 2 < Cin) load_stage(buf ^ 1, ci + 2);

#pragma unroll
        for (int ch = 0; ch < 2; ch++) {
            u64 p[4][5];
#pragma unroll
            for (int r = 0; r < 4; r++) {
                const u64* rowE = (const u64*)&s_E[buf][ch][ty * 2 + r][px0];
                const u64* rowO = (const u64*)&s_O[buf][ch][ty * 2 + r][px0];
                p[r][1] = rowE[0];
                p[r][3] = rowE[1];
                p[r][0] = rowO[0];
                p[r][2] = rowO[1];
                p[r][4] = rowO[2];
            }
#pragma unroll
            for (int k = 0; k < 9; k++) {
                const int r = k / 3, s = k % 3;
                const ulonglong2* wk = (const ulonglong2*)&s_w[buf][ch][k][0];
#pragma unroll
                for (int op = 0; op < 4; op++) {
                    ulonglong2 wq = wk[op];
                    const int o0 = 2 * op, o1 = 2 * op + 1;
                    acc[o0][0][0] = ffma2(p[r + 0][s],     wq.x, acc[o0][0][0]);
                    acc[o0][0][1] = ffma2(p[r + 0][s + 2], wq.x, acc[o0][0][1]);
                    acc[o0][1][0] = ffma2(p[r + 1][s],     wq.x, acc[o0][1][0]);
                    acc[o0][1][1] = ffma2(p[r + 1][s + 2], wq.x, acc[o0][1][1]);
                    acc[o1][0][0] = ffma2(p[r + 0][s],     wq.y, acc[o1][0][0]);
                    acc[o1][0][1] = ffma2(p[r + 0][s + 2], wq.y, acc[o1][0][1]);
                    acc[o1][1][0] = ffma2(p[r + 1][s],     wq.y, acc[o1][1][0]);
                    acc[o1][1][1] = ffma2(p[r + 1][s + 2], wq.y, acc[o1][1][1]);
                }
            }
        }
        __syncthreads();
    }

#pragma unroll
    for (int o = 0; o < 8; o++) {
        float bv = bias[oc0 + o];
#pragma unroll
        for (int i = 0; i < 2; i++) {
            int yy = y0 + ty * 2 + i;
            float* op = out + ((size_t)b * Cout_ + oc0 + o) * HWSZ + yy * WW + px0;
#pragma unroll
            for (int jp = 0; jp < 2; jp++) {
                float2 v = upk(acc[o][i][jp]);
                v.x += bv; v.y += bv;
                if (lrelu) {
                    v.x = (v.x >= 0.f) ? v.x : 0.1f * v.x;
                    v.y = (v.y >= 0.f) ? v.y : 0.1f * v.y;
                }
                ((float2*)op)[jp] = v;
            }
        }
    }
}

// ---------------------------------------------------------------------------
// Deformable conv v3: 1 px/thread (occ 4, single wave), two-phase (g,k) body:
// Phase A: tap geometry + batched gathers for all 8 channels (32 LDGs in flight)
// Phase B: dense weight FMA (256 FFMA2) with no loads in the dependency chain.
// blockDim = (32,4); grid = (W/32, H/4, B) = 512 CTAs.
// ---------------------------------------------------------------------------
__global__ void __launch_bounds__(128, 4)
deform_k(const float* __restrict__ x, const float* __restrict__ o4,
         const float* __restrict__ wt, const float* __restrict__ bias,
         float* __restrict__ out) {
    const int tx = threadIdx.x, ty = threadIdx.y;
    const int tid = ty * 32 + tx;
    const int b   = blockIdx.z;
    const int px  = blockIdx.x * 32 + tx;
    const int py  = blockIdx.y * 4 + ty;
    const int p   = py * WW + px;

    __shared__ __align__(16) u64 s_w[8 * 9 * 32];  // [c][k][oc-pair]

    u64 acc[32];
#pragma unroll
    for (int q = 0; q < 32; q++) acc[q] = 0ull;

    const float* xb = x + (size_t)b * CIN * HWSZ;
    const float* ob = o4 + (size_t)b * (27 * DG) * HWSZ;

    for (int g = 0; g < DG; g++) {
        __syncthreads();
        const u64* wg = (const u64*)(wt + (size_t)g * 8 * 9 * 64);
        for (int i = tid; i < 8 * 9 * 32; i += 128) s_w[i] = wg[i];
        __syncthreads();

        const float* xg = xb + (size_t)g * 8 * HWSZ;

        for (int k = 0; k < KK; k++) {
            // ---- Phase A: tap geometry ----
            float dy = 10.f * fast_tanh(ob[(size_t)(g * 18 + 2 * k) * HWSZ + p]);
            float dx = 10.f * fast_tanh(ob[(size_t)(g * 18 + 2 * k + 1) * HWSZ + p]);
            float m  = fast_sigmoid(ob[(size_t)(288 + g * 9 + k) * HWSZ + p]);

            float fy = (float)py - 1.f + (float)(k / 3) + dy;
            float fx = (float)px - 1.f + (float)(k % 3) + dx;
            float y0f = floorf(fy), x0f = floorf(fx);
            float ly = fy - y0f, lx = fx - x0f;
            int y0 = (int)y0f, x0 = (int)x0f;
            int y1 = y0 + 1, x1 = x0 + 1;

            bool vy0 = (y0 >= 0) && (y0 < HH);
            bool vy1 = (y1 >= 0) && (y1 < HH);
            bool vx0 = (x0 >= 0) && (x0 < WW);
            bool vx1 = (x1 >= 0) && (x1 < WW);

            float w00 = (1.f - ly) * (1.f - lx) * ((vy0 && vx0) ? m : 0.f);
            float w01 = (1.f - ly) * lx         * ((vy0 && vx1) ? m : 0.f);
            float w10 = ly * (1.f - lx)         * ((vy1 && vx0) ? m : 0.f);
            float w11 = ly * lx                 * ((vy1 && vx1) ? m : 0.f);

            int yc0 = min(max(y0, 0), HH - 1);
            int yc1 = min(max(y1, 0), HH - 1);
            int xc0 = min(max(x0, 0), WW - 1);
            int xc1 = min(max(x1, 0), WW - 1);
            int i00 = yc0 * WW + xc0, i01 = yc0 * WW + xc1;
            int i10 = yc1 * WW + xc0, i11 = yc1 * WW + xc1;

            // ---- Phase A': batched gathers (all 8 channels, 32 LDGs) ----
            float v[8];
#pragma unroll
            for (int c = 0; c < 8; c++) {
                const float* xc = xg + (size_t)c * HWSZ;
                float a = __ldg(&xc[i00]);
                float bq = __ldg(&xc[i01]);
                float d = __ldg(&xc[i10]);
                float e = __ldg(&xc[i11]);
                v[c] = w00 * a + w01 * bq + w10 * d + w11 * e;
            }

            // ---- Phase B: dense weight FMA (no loads in chain) ----
#pragma unroll
            for (int c = 0; c < 8; c++) {
                u64 v2 = pk2(v[c], v[c]);
                const ulonglong2* wp = (const ulonglong2*)&s_w[(c * 9 + k) * 32];
#pragma unroll
                for (int q = 0; q < 16; q++) {
                    ulonglong2 wq = wp[q];
                    acc[q * 2 + 0] = ffma2(v2, wq.x, acc[q * 2 + 0]);
                    acc[q * 2 + 1] = ffma2(v2, wq.y, acc[q * 2 + 1]);
                }
            }
        }
    }

    float* outb = out + (size_t)b * COUT * HWSZ + p;
#pragma unroll
    for (int q = 0; q < 32; q++) {
        float2 bv = ((const float2*)bias)[q];
        float2 a = upk(acc[q]);
        outb[(size_t)(2 * q + 0) * HWSZ] = a.x + bv.x;
        outb[(size_t)(2 * q + 1) * HWSZ] = a.y + bv.y;
    }
}

// ---------------------------------------------------------------------------
// Launcher
// ---------------------------------------------------------------------------
extern "C" void kernel_launch(void* const* d_in, const int* in_sizes, int n_in,
                              void* d_out, int out_size) {
    const float* x          = (const float*)d_in[0];
    const float* extra_feat = (const float*)d_in[1];
    const float* w1 = (const float*)d_in[2];
    const float* b1 = (const float*)d_in[3];
    const float* w2 = (const float*)d_in[4];
    const float* b2 = (const float*)d_in[5];
    const float* w3 = (const float*)d_in[6];
    const float* b3 = (const float*)d_in[7];
    const float* w4 = (const float*)d_in[8];
    const float* b4 = (const float*)d_in[9];
    const float* weight = (const float*)d_in[10];
    const float* bias   = (const float*)d_in[11];
    float* out = (float*)d_out;

    float *t1, *t2, *o4, *wt;
    cudaGetSymbolAddress((void**)&t1, g_t1);
    cudaGetSymbolAddress((void**)&t2, g_t2);
    cudaGetSymbolAddress((void**)&o4, g_o4);
    cudaGetSymbolAddress((void**)&wt, g_wt);

    dim3 blk(32, 4);

    // Transpose deform weight (only consumer is deform_k, last kernel)
    {
        int n = CIN * KK * COUT;
        transpose_weight_k<<<(n + 255) / 256, 256>>>(weight, wt);
    }

    // conv1: extra_feat (192ch) -> t1 (64ch), lrelu
    conv3x3_k<<<dim3(HH / 8, COUT / 8, BATCH), blk>>>(extra_feat, w1, b1, t1, 3 * COUT, COUT, 1);
    // conv2: t1 -> t2, lrelu
    conv3x3_k<<<dim3(HH / 8, COUT / 8, BATCH), blk>>>(t1, w2, b2, t2, COUT, COUT, 1);
    // conv3: t2 -> t1, lrelu
    conv3x3_k<<<dim3(HH / 8, COUT / 8, BATCH), blk>>>(t2, w3, b3, t1, COUT, COUT, 1);
    // conv4: t1 -> o4 (432ch), no activation (fused into deform)
    conv3x3_k<<<dim3(HH / 8, (27 * DG) / 8, BATCH), blk>>>(t1, w4, b4, o4, COUT, 27 * DG, 0);
    // deformable conv: x + o4 -> out (1 px/thread, two-phase body)
    deform_k<<<dim3(WW / 32, HH / 4, BATCH), blk>>>(x, o4, wt, bias, out);
}

// round 7
// speedup vs baseline: 1.0766x; 1.0190x over previous
#include <cuda_runtime.h>
#include <cuda_bf16.h>
#include <math.h>

// Problem constants
constexpr int BATCH = 4;
constexpr int CIN   = 128;
constexpr int COUT  = 64;
constexpr int HH    = 128;
constexpr int WW    = 128;
constexpr int HWSZ  = HH * WW;
constexpr int DG    = 16;
constexpr int KK    = 9;

// Scratch (static device buffers; allocation APIs are forbidden)
__device__ float g_t1[(size_t)BATCH * COUT * HWSZ];
__device__ float g_t2[(size_t)BATCH * COUT * HWSZ];
__device__ float g_o4[(size_t)BATCH * (27 * DG) * HWSZ];      // 432 channels
__device__ __align__(16) float g_wt[(size_t)CIN * KK * COUT]; // transposed deform weight [cin][k][o]

// ---------------------------------------------------------------------------
// Packed f32x2 helpers (sm_103a FFMA2 path)
// ---------------------------------------------------------------------------
typedef unsigned long long u64;

__device__ __forceinline__ u64 ffma2(u64 a, u64 b, u64 c) {
    u64 d;
    asm("fma.rn.f32x2 %0, %1, %2, %3;" : "=l"(d) : "l"(a), "l"(b), "l"(c));
    return d;
}
__device__ __forceinline__ u64 pk2(float lo, float hi) {
    u64 r;
    asm("mov.b64 %0, {%1, %2};" : "=l"(r) : "f"(lo), "f"(hi));
    return r;
}
__device__ __forceinline__ float2 upk(u64 v) {
    float2 r;
    asm("mov.b64 {%0, %1}, %2;" : "=f"(r.x), "=f"(r.y) : "l"(v));
    return r;
}
__device__ __forceinline__ float fast_tanh(float x) {
    return 1.f - 2.f / (__expf(2.f * x) + 1.f);
}
__device__ __forceinline__ float fast_sigmoid(float x) {
    return 1.f / (1.f + __expf(-x));
}

// ---------------------------------------------------------------------------
// Transpose deform weight (COUT, CIN, 3, 3) -> [cin][k][o]
// ---------------------------------------------------------------------------
__global__ void transpose_weight_k(const float* __restrict__ w, float* __restrict__ wt) {
    int idx = blockIdx.x * blockDim.x + threadIdx.x;
    int n = CIN * KK * COUT;
    if (idx >= n) return;
    int o   = idx % COUT;
    int k   = (idx / COUT) % KK;
    int cin = idx / (COUT * KK);
    wt[idx] = w[((size_t)o * CIN + cin) * KK + k];
}

// ---------------------------------------------------------------------------
// Direct 3x3 conv, pad=1, stride=1, optional leaky-relu(0.1). (unchanged R4)
// ---------------------------------------------------------------------------
__global__ void __launch_bounds__(128, 4)
conv3x3_k(const float* __restrict__ in, const float* __restrict__ wgt,
          const float* __restrict__ bias, float* __restrict__ out,
          int Cin, int Cout_, int lrelu) {
    const int tx   = threadIdx.x;        // 0..31
    const int ty   = threadIdx.y;        // 0..3
    const int tid  = ty * 32 + tx;
    const int lane = tid & 31;
    const int warp = tid >> 5;
    const int y0   = blockIdx.x * 8;
    const int oc0  = blockIdx.y * 8;
    const int b    = blockIdx.z;
    const int px0  = tx * 4;

    __shared__ __align__(16) float s_E[2][2][10][132];  // [buf][ch][row][pos]
    __shared__ __align__(16) float s_O[2][2][10][132];
    __shared__ __align__(16) u64   s_w[2][2][9][8];     // [buf][ch][k][o] dup-packed

    for (int i = tid; i < 40; i += 128) {
        int bu = i / 20, ch = (i / 10) % 2, t = i % 10;
        s_O[bu][ch][t][0]   = 0.f;
        s_O[bu][ch][t][129] = 0.f;
    }

    u64 acc[8][2][2];
#pragma unroll
    for (int o = 0; o < 8; o++)
#pragma unroll
        for (int i = 0; i < 2; i++) { acc[o][i][0] = 0ull; acc[o][i][1] = 0ull; }

    const float* inb = in + (size_t)b * Cin * HWSZ;

    auto load_stage = [&](int buf, int ci) {
#pragma unroll
        for (int rr = warp; rr < 20; rr += 4) {
            int ch = rr / 10, t = rr % 10;
            int gy = y0 - 1 + t;
            float4 v = make_float4(0.f, 0.f, 0.f, 0.f);
            if (gy >= 0 && gy < HH) {
                const float* src = inb + (size_t)(ci + ch) * HWSZ + gy * WW;
                v = ((const float4*)src)[lane];
            }
            *((float4*)&s_E[buf][ch][t][lane * 4]) = v;
            float* dO = &s_O[buf][ch][t][lane * 4 + 1];
            dO[0] = v.x; dO[1] = v.y; dO[2] = v.z; dO[3] = v.w;
        }
        for (int i = tid; i < 144; i += 128) {
            int ch = i / 72, r = i % 72;
            int k = r / 8, o = r % 8;
            float w = wgt[((size_t)(oc0 + o) * Cin + ci + ch) * 9 + k];
            s_w[buf][ch][k][o] = pk2(w, w);
        }
    };

    load_stage(0, 0);
    __syncthreads();

    for (int ci = 0; ci < Cin; ci += 2) {
        const int buf = (ci >> 1) & 1;
        if (ci + 2 < Cin) load_stage(buf ^ 1, ci + 2);

#pragma unroll
        for (int ch = 0; ch < 2; ch++) {
            u64 p[4][5];
#pragma unroll
            for (int r = 0; r < 4; r++) {
                const u64* rowE = (const u64*)&s_E[buf][ch][ty * 2 + r][px0];
                const u64* rowO = (const u64*)&s_O[buf][ch][ty * 2 + r][px0];
                p[r][1] = rowE[0];
                p[r][3] = rowE[1];
                p[r][0] = rowO[0];
                p[r][2] = rowO[1];
                p[r][4] = rowO[2];
            }
#pragma unroll
            for (int k = 0; k < 9; k++) {
                const int r = k / 3, s = k % 3;
                const ulonglong2* wk = (const ulonglong2*)&s_w[buf][ch][k][0];
#pragma unroll
                for (int op = 0; op < 4; op++) {
                    ulonglong2 wq = wk[op];
                    const int o0 = 2 * op, o1 = 2 * op + 1;
                    acc[o0][0][0] = ffma2(p[r + 0][s],     wq.x, acc[o0][0][0]);
                    acc[o0][0][1] = ffma2(p[r + 0][s + 2], wq.x, acc[o0][0][1]);
                    acc[o0][1][0] = ffma2(p[r + 1][s],     wq.x, acc[o0][1][0]);
                    acc[o0][1][1] = ffma2(p[r + 1][s + 2], wq.x, acc[o0][1][1]);
                    acc[o1][0][0] = ffma2(p[r + 0][s],     wq.y, acc[o1][0][0]);
                    acc[o1][0][1] = ffma2(p[r + 0][s + 2], wq.y, acc[o1][0][1]);
                    acc[o1][1][0] = ffma2(p[r + 1][s],     wq.y, acc[o1][1][0]);
                    acc[o1][1][1] = ffma2(p[r + 1][s + 2], wq.y, acc[o1][1][1]);
                }
            }
        }
        __syncthreads();
    }

#pragma unroll
    for (int o = 0; o < 8; o++) {
        float bv = bias[oc0 + o];
#pragma unroll
        for (int i = 0; i < 2; i++) {
            int yy = y0 + ty * 2 + i;
            float* op = out + ((size_t)b * Cout_ + oc0 + o) * HWSZ + yy * WW + px0;
#pragma unroll
            for (int jp = 0; jp < 2; jp++) {
                float2 v = upk(acc[o][i][jp]);
                v.x += bv; v.y += bv;
                if (lrelu) {
                    v.x = (v.x >= 0.f) ? v.x : 0.1f * v.x;
                    v.y = (v.y >= 0.f) ? v.y : 0.1f * v.y;
                }
                ((float2*)op)[jp] = v;
            }
        }
    }
}

// ---------------------------------------------------------------------------
// Deformable conv v4: software-pipelined.
//  - offsets for iteration i+1 prefetched before iteration i's FMA block
//  - gathers for iteration i issued, then Phase B (weight FMA) for iteration
//    i-1 runs while they fly, then i's bilinear combine.
// blockDim = (32,8) = 256 thr; grid = (W/32, H/8, B) = 256 CTAs (single wave,
// occ 2, 16 warps/SM).
// ---------------------------------------------------------------------------
__global__ void __launch_bounds__(256, 2)
deform_k(const float* __restrict__ x, const float* __restrict__ o4,
         const float* __restrict__ wt, const float* __restrict__ bias,
         float* __restrict__ out) {
    const int tx = threadIdx.x, ty = threadIdx.y;
    const int tid = ty * 32 + tx;
    const int b   = blockIdx.z;
    const int px  = blockIdx.x * 32 + tx;
    const int py  = blockIdx.y * 8 + ty;
    const int p   = py * WW + px;

    __shared__ __align__(16) u64 s_w[8 * 9 * 32];  // [c][k][oc-pair]

    u64 acc[32];
#pragma unroll
    for (int q = 0; q < 32; q++) acc[q] = 0ull;

    const float* xb = x + (size_t)b * CIN * HWSZ;
    const float* ob = o4 + (size_t)b * (27 * DG) * HWSZ + p;   // p folded in

    // prefetched raw offset/mask for the *next* iteration
    float r_dy = __ldg(ob);
    float r_dx = __ldg(ob + HWSZ);
    float r_m  = __ldg(ob + (size_t)288 * HWSZ);

    float vprev[8];

    // Phase B: dense weight FMA for iteration with kernel-tap index kidx,
    // consuming vprev[]. Reads s_w (must run before s_w is restaged).
    auto phaseB = [&](int kidx) {
#pragma unroll
        for (int c = 0; c < 8; c++) {
            u64 v2 = pk2(vprev[c], vprev[c]);
            const ulonglong2* wp = (const ulonglong2*)&s_w[(c * 9 + kidx) * 32];
#pragma unroll
            for (int q = 0; q < 16; q++) {
                ulonglong2 wq = wp[q];
                acc[q * 2 + 0] = ffma2(v2, wq.x, acc[q * 2 + 0]);
                acc[q * 2 + 1] = ffma2(v2, wq.y, acc[q * 2 + 1]);
            }
        }
    };

    for (int g = 0; g < DG; g++) {
        // finish previous group's k=8 Phase B before s_w is overwritten
        if (g > 0) phaseB(8);
        __syncthreads();
        {
            const u64* wg = (const u64*)(wt + (size_t)g * 8 * 9 * 64);
            for (int i = tid; i < 8 * 9 * 32; i += 256) s_w[i] = wg[i];
        }
        __syncthreads();

        const float* xg  = xb + (size_t)g * 8 * HWSZ;
        const float* obg = ob + (size_t)g * 18 * HWSZ;          // dy/dx for this g
        const float* obm = ob + (size_t)(288 + g * 9) * HWSZ;   // mask for this g

#pragma unroll 1
        for (int k = 0; k < KK; k++) {
            // ---- geometry from prefetched raw values ----
            float dy = 10.f * fast_tanh(r_dy);
            float dx = 10.f * fast_tanh(r_dx);
            float m  = fast_sigmoid(r_m);

            float fy = (float)py - 1.f + (float)(k / 3) + dy;
            float fx = (float)px - 1.f + (float)(k % 3) + dx;
            float y0f = floorf(fy), x0f = floorf(fx);
            float ly = fy - y0f, lx = fx - x0f;
            int y0 = (int)y0f, x0 = (int)x0f;
            int y1 = y0 + 1, x1 = x0 + 1;

            bool vy0 = (y0 >= 0) && (y0 < HH);
            bool vy1 = (y1 >= 0) && (y1 < HH);
            bool vx0 = (x0 >= 0) && (x0 < WW);
            bool vx1 = (x1 >= 0) && (x1 < WW);

            float w00 = (1.f - ly) * (1.f - lx) * ((vy0 && vx0) ? 1.f : 0.f);
            float w01 = (1.f - ly) * lx         * ((vy0 && vx1) ? 1.f : 0.f);
            float w10 = ly * (1.f - lx)         * ((vy1 && vx0) ? 1.f : 0.f);
            float w11 = ly * lx                 * ((vy1 && vx1) ? 1.f : 0.f);

            int yc0 = min(max(y0, 0), HH - 1);
            int yc1 = min(max(y1, 0), HH - 1);
            int xc0 = min(max(x0, 0), WW - 1);
            int xc1 = min(max(x1, 0), WW - 1);
            int i00 = yc0 * WW + xc0, i01 = yc0 * WW + xc1;
            int i10 = yc1 * WW + xc0, i11 = yc1 * WW + xc1;

            // ---- issue all 32 gathers (in flight during Phase B below) ----
            float t[32];
#pragma unroll
            for (int c = 0; c < 8; c++) {
                const float* xc = xg + (size_t)c * HWSZ;
                t[c * 4 + 0] = __ldg(&xc[i00]);
                t[c * 4 + 1] = __ldg(&xc[i01]);
                t[c * 4 + 2] = __ldg(&xc[i10]);
                t[c * 4 + 3] = __ldg(&xc[i11]);
            }

            // ---- prefetch next iteration's raw offsets ----
            if (k < 8) {
                r_dy = __ldg(obg + (size_t)(2 * k + 2) * HWSZ);
                r_dx = __ldg(obg + (size_t)(2 * k + 3) * HWSZ);
                r_m  = __ldg(obm + (size_t)(k + 1) * HWSZ);
            } else if (g < DG - 1) {
                r_dy = __ldg(obg + (size_t)18 * HWSZ);
                r_dx = __ldg(obg + (size_t)19 * HWSZ);
                r_m  = __ldg(obm + (size_t)9 * HWSZ);
            }

            // ---- Phase B for the PREVIOUS k (no dependence on t[]) ----
            if (k > 0) phaseB(k - 1);

            // ---- combine gathers into vprev (waits on t[]) ----
#pragma unroll
            for (int c = 0; c < 8; c++) {
                vprev[c] = m * (w00 * t[c * 4 + 0] + w01 * t[c * 4 + 1]
                              + w10 * t[c * 4 + 2] + w11 * t[c * 4 + 3]);
            }
        }
    }
    // last iteration's Phase B
    phaseB(8);

    float* outb = out + (size_t)b * COUT * HWSZ + p;
#pragma unroll
    for (int q = 0; q < 32; q++) {
        float2 bv = ((const float2*)bias)[q];
        float2 a = upk(acc[q]);
        outb[(size_t)(2 * q + 0) * HWSZ] = a.x + bv.x;
        outb[(size_t)(2 * q + 1) * HWSZ] = a.y + bv.y;
    }
}

// ---------------------------------------------------------------------------
// Launcher
// ---------------------------------------------------------------------------
extern "C" void kernel_launch(void* const* d_in, const int* in_sizes, int n_in,
                              void* d_out, int out_size) {
    const float* x          = (const float*)d_in[0];
    const float* extra_feat = (const float*)d_in[1];
    const float* w1 = (const float*)d_in[2];
    const float* b1 = (const float*)d_in[3];
    const float* w2 = (const float*)d_in[4];
    const float* b2 = (const float*)d_in[5];
    const float* w3 = (const float*)d_in[6];
    const float* b3 = (const float*)d_in[7];
    const float* w4 = (const float*)d_in[8];
    const float* b4 = (const float*)d_in[9];
    const float* weight = (const float*)d_in[10];
    const float* bias   = (const float*)d_in[11];
    float* out = (float*)d_out;

    float *t1, *t2, *o4, *wt;
    cudaGetSymbolAddress((void**)&t1, g_t1);
    cudaGetSymbolAddress((void**)&t2, g_t2);
    cudaGetSymbolAddress((void**)&o4, g_o4);
    cudaGetSymbolAddress((void**)&wt, g_wt);

    dim3 blk(32, 4);

    // Transpose deform weight (only consumer is deform_k, last kernel)
    {
        int n = CIN * KK * COUT;
        transpose_weight_k<<<(n + 255) / 256, 256>>>(weight, wt);
    }

    // conv1: extra_feat (192ch) -> t1 (64ch), lrelu
    conv3x3_k<<<dim3(HH / 8, COUT / 8, BATCH), blk>>>(extra_feat, w1, b1, t1, 3 * COUT, COUT, 1);
    // conv2: t1 -> t2, lrelu
    conv3x3_k<<<dim3(HH / 8, COUT / 8, BATCH), blk>>>(t1, w2, b2, t2, COUT, COUT, 1);
    // conv3: t2 -> t1, lrelu
    conv3x3_k<<<dim3(HH / 8, COUT / 8, BATCH), blk>>>(t2, w3, b3, t1, COUT, COUT, 1);
    // conv4: t1 -> o4 (432ch), no activation (fused into deform)
    conv3x3_k<<<dim3(HH / 8, (27 * DG) / 8, BATCH), blk>>>(t1, w4, b4, o4, COUT, 27 * DG, 0);
    // deformable conv: x + o4 -> out (software-pipelined)
    deform_k<<<dim3(WW / 32, HH / 8, BATCH), dim3(32, 8)>>>(x, o4, wt, bias, out);
}